// round 8
// baseline (speedup 1.0000x reference)
#include <cuda_runtime.h>
#include <math.h>

#define WW 512
#define HH 512
#define NIMG 8
#define HWSZ (HH * WW)
#define NPLANES 16            // 2 streams (p, target) x 8 samples
#define TOTALSZ (NPLANES * HWSZ)
#define NITER 50

// ---- open-init sweep config (float4 lanes, 5 strips x 120 cols) ----------
#define STRIPS 5
#define CHUNK_ROWS 16
#define CHUNKS 32             // 512 / 16
#define WARPS_TOTAL (STRIPS * CHUNKS * NPLANES)   // 2560
#define SWEEP_BLOCK 256
#define SWEEP_GRID (WARPS_TOTAL / (SWEEP_BLOCK / 32))  // 320

// ---- fused-2 iteration config (float2 lanes, 10 strips x 56 cols) --------
#define STRIPS2 10
#define WARPS2 (STRIPS2 * CHUNKS * NPLANES)       // 5120
#define IT2_BLOCK 128
#define IT2_GRID (WARPS2 / (IT2_BLOCK / 32))      // 1280

// Static scratch (no allocations allowed in kernel_launch)
__device__ float g_p[NIMG * HWSZ];     // sigmoid(output), kept for final reduction
__device__ float g_imgA[TOTALSZ];      // ping
__device__ float g_imgB[TOTALSZ];      // pong
__device__ float g_skel[TOTALSZ];      // skeleton accumulators (both streams)
__device__ double g_sums[NIMG][7];     // per-sample reduction accumulators

// ---------------------------------------------------------------------------
// float4 helpers (open-init)
// ---------------------------------------------------------------------------
__device__ __forceinline__ float4 f44(float v) { return make_float4(v, v, v, v); }
__device__ __forceinline__ float4 min4(float4 a, float4 b) {
    return make_float4(fminf(a.x, b.x), fminf(a.y, b.y), fminf(a.z, b.z), fminf(a.w, b.w));
}
__device__ __forceinline__ float4 max4(float4 a, float4 b) {
    return make_float4(fmaxf(a.x, b.x), fmaxf(a.y, b.y), fmaxf(a.z, b.z), fmaxf(a.w, b.w));
}
__device__ __forceinline__ float4 vmin3(float4 a, float4 b, float4 c) { return min4(min4(a, b), c); }
__device__ __forceinline__ float4 vmax3(float4 a, float4 b, float4 c) { return max4(max4(a, b), c); }
__device__ __forceinline__ float4 hmin3(float4 v, int lane) {
    float L = __shfl_up_sync(0xffffffffu, v.w, 1);
    float R = __shfl_down_sync(0xffffffffu, v.x, 1);
    if (lane == 0)  L = INFINITY;
    if (lane == 31) R = INFINITY;
    float m01 = fminf(v.x, v.y), m23 = fminf(v.z, v.w);
    return make_float4(fminf(L, m01), fminf(m01, v.z), fminf(v.y, m23), fminf(m23, R));
}
__device__ __forceinline__ float4 hmax3(float4 v, int lane) {
    float L = __shfl_up_sync(0xffffffffu, v.w, 1);
    float R = __shfl_down_sync(0xffffffffu, v.x, 1);
    if (lane == 0)  L = -INFINITY;
    if (lane == 31) R = -INFINITY;
    float m01 = fmaxf(v.x, v.y), m23 = fmaxf(v.z, v.w);
    return make_float4(fmaxf(L, m01), fmaxf(m01, v.z), fmaxf(v.y, m23), fmaxf(m23, R));
}
__device__ __forceinline__ float4 relu_sub(float4 a, float4 b) {
    return make_float4(fmaxf(0.0f, a.x - b.x), fmaxf(0.0f, a.y - b.y),
                       fmaxf(0.0f, a.z - b.z), fmaxf(0.0f, a.w - b.w));
}

// ---------------------------------------------------------------------------
// float2 helpers (fused iteration)
// ---------------------------------------------------------------------------
__device__ __forceinline__ float2 f22(float v) { return make_float2(v, v); }
__device__ __forceinline__ float2 min2(float2 a, float2 b) {
    return make_float2(fminf(a.x, b.x), fminf(a.y, b.y));
}
__device__ __forceinline__ float2 max2(float2 a, float2 b) {
    return make_float2(fmaxf(a.x, b.x), fmaxf(a.y, b.y));
}
__device__ __forceinline__ float2 vmin3_2(float2 a, float2 b, float2 c) { return min2(min2(a, b), c); }
__device__ __forceinline__ float2 vmax3_2(float2 a, float2 b, float2 c) { return max2(max2(a, b), c); }
__device__ __forceinline__ float2 hmin3_2(float2 v, int lane) {
    float L = __shfl_up_sync(0xffffffffu, v.y, 1);
    float R = __shfl_down_sync(0xffffffffu, v.x, 1);
    if (lane == 0)  L = INFINITY;
    if (lane == 31) R = INFINITY;
    float m = fminf(v.x, v.y);
    return make_float2(fminf(L, m), fminf(m, R));
}
__device__ __forceinline__ float2 hmax3_2(float2 v, int lane) {
    float L = __shfl_up_sync(0xffffffffu, v.y, 1);
    float R = __shfl_down_sync(0xffffffffu, v.x, 1);
    if (lane == 0)  L = -INFINITY;
    if (lane == 31) R = -INFINITY;
    float m = fmaxf(v.x, v.y);
    return make_float2(fmaxf(L, m), fmaxf(m, R));
}
__device__ __forceinline__ float2 relu_sub2(float2 a, float2 b) {
    return make_float2(fmaxf(0.0f, a.x - b.x), fmaxf(0.0f, a.y - b.y));
}
__device__ __forceinline__ float2 maskneg2(float2 v, bool ok) {
    return ok ? v : f22(-INFINITY);
}
__device__ __forceinline__ void skel_upd2(float2& s, float2 d) {
    s.x += fmaxf(0.0f, fmaf(-s.x, d.x, d.x));
    s.y += fmaxf(0.0f, fmaf(-s.y, d.y, d.y));
}

// ---------------------------------------------------------------------------
// Init: p = sigmoid(output); imgA[stream0] = p, imgA[stream1] = target
// ---------------------------------------------------------------------------
__global__ void k_init(const float4* __restrict__ out, const float4* __restrict__ tgt) {
    int i = blockIdx.x * blockDim.x + threadIdx.x;
    int stride = gridDim.x * blockDim.x;
    float4* gp = (float4*)g_p;
    float4* ga = (float4*)g_imgA;
    float4* gb = (float4*)(g_imgA + NIMG * HWSZ);
    const int n4 = NIMG * HWSZ / 4;
    for (; i < n4; i += stride) {
        float4 o = out[i];
        float4 v;
        v.x = 1.0f / (1.0f + expf(-o.x));
        v.y = 1.0f / (1.0f + expf(-o.y));
        v.z = 1.0f / (1.0f + expf(-o.z));
        v.w = 1.0f / (1.0f + expf(-o.w));
        gp[i] = v;
        ga[i] = v;
        gb[i] = tgt[i];
    }
}

// ---------------------------------------------------------------------------
// Warp-sweep open-init:  skel = relu(img - dilate(erode(img)))
// ---------------------------------------------------------------------------
__global__ void __launch_bounds__(SWEEP_BLOCK, 3) k_open_init() {
    const int lane = threadIdx.x & 31;
    const int gw = (blockIdx.x * SWEEP_BLOCK + threadIdx.x) >> 5;
    const int strip = gw % STRIPS;
    const int t = gw / STRIPS;
    const int chunk = t & (CHUNKS - 1);
    const int z = t >> 5;

    const float* __restrict__ src = g_imgA + z * HWSZ;
    float* __restrict__ skel = g_skel + z * HWSZ;

    const int c0 = strip * 120 - 4 + 4 * lane;
    const bool colok = (c0 >= 0) && (c0 < WW);
    const bool stok = (lane >= 1) && (lane <= 30) && (c0 < WW);
    const int r0 = chunk * CHUNK_ROWS;
    const int ylim = r0 + 2;

    int y = r0 - 2;
    const float* srcp = src + y * WW + c0;
    float* const skb = skel + c0;

    float4 ia = f44(INFINITY), ib = f44(INFINITY), ic;
    float4 ha = f44(-INFINITY), hb = f44(-INFINITY), hc;

#define OPEN_STEP(IA, IB, IC, HA, HB, HC)                                      \
    {                                                                          \
        bool ldok = colok && ((unsigned)y < (unsigned)HH);                     \
        IC = ldok ? *(const float4*)srcp : f44(INFINITY);                      \
        float4 e1_ = min4(vmin3(IA, IB, IC), hmin3(IB, lane));                 \
        if (!colok || (unsigned)(y - 1) >= (unsigned)HH) e1_ = f44(-INFINITY); \
        HC = hmax3(e1_, lane);                                                 \
        if (y >= ylim) {                                                       \
            float4 d_ = vmax3(HA, HB, HC);                                     \
            if (stok) {                                                        \
                float4 o_ = relu_sub(IA, d_);                                  \
                *(float4*)(skb + (y - 2) * WW) = o_;                           \
            }                                                                  \
        }                                                                      \
        ++y;                                                                   \
        srcp += WW;                                                            \
    }

#pragma unroll 1
    for (int k = 0; k < 6; ++k) {
        OPEN_STEP(ia, ib, ic, ha, hb, hc);
        OPEN_STEP(ib, ic, ia, hb, hc, ha);
        OPEN_STEP(ic, ia, ib, hc, ha, hb);
    }
    OPEN_STEP(ia, ib, ic, ha, hb, hc);
    OPEN_STEP(ib, ic, ia, hb, hc, ha);
#undef OPEN_STEP
}

// ---------------------------------------------------------------------------
// Fused TWO skeleton iterations, float2 lanes, templated interior fast path.
//   E1 = erode(img); E2 = erode(E1) -> new img; E3 = erode(E2)
//   delta1 = relu(E1 - dilate(E2)); delta2 = relu(E2 - dilate(E3))
//   skel row update applies both deltas in-register, one load + one store.
// Vertical/horizontal halo 4.  RIN: rows never OOB.  CIN: cols never OOB.
// ---------------------------------------------------------------------------
template<bool RIN, bool CIN>
__device__ __forceinline__ void it2_body(
    const float* __restrict__ src, float* __restrict__ dst,
    float* __restrict__ skel, int lane, int strip, int r0)
{
    const int c0 = strip * 56 - 4 + 2 * lane;
    const bool colok = CIN || ((c0 >= 0) && (c0 < WW));
    const bool stok = (lane >= 2) && (lane <= 29) && (CIN || (c0 < WW));
    const int yD1 = r0 + 3;    // first step producing delta1 (row y-3)
    const int yOUT = r0 + 4;   // first step producing output (row y-4)

    int y = r0 - 4;
    float2 pf;
    {
        bool ldok = colok && (RIN || (unsigned)y < (unsigned)HH);
        pf = ldok ? *(const float2*)(src + y * WW + c0) : f22(INFINITY);
    }
    const float* srcp = src + (y + 1) * WW + c0;
    float* const skb = skel + c0;
    float* const dsb = dst + c0;

    float2 ia = f22(INFINITY), ib = f22(INFINITY), ic;       // I ring
    float2 ea = f22(INFINITY), eb = f22(INFINITY), ec;       // E1 ring
    float2 fa = f22(INFINITY), fb = f22(INFINITY), fc;       // E2 ring
    float2 ha = f22(-INFINITY), hb = f22(-INFINITY), hc;     // H = hmax(E2)
    float2 ba = f22(-INFINITY), bb = f22(-INFINITY), bc;     // Hb = hmax(E3)
    float2 dprev = f22(0.0f);                                // delta1[y-4]
    float2 spf = f22(0.0f);                                  // skel prefetch

#define STEP2(IA, IB, IC, EA, EB, EC, FA, FB, FC, HA, HB, HC, BA, BB, BC)      \
    {                                                                          \
        float2 icur = pf;                                                      \
        {                                                                      \
            bool ldok = colok && (RIN || (unsigned)(y + 1) < (unsigned)HH);    \
            pf = ldok ? *(const float2*)srcp : f22(INFINITY);                  \
            srcp += WW;                                                        \
        }                                                                      \
        IC = icur;                                                             \
        EC = min2(vmin3_2(IA, IB, IC), hmin3_2(IB, lane));   /* E1[y-1] */     \
        FC = min2(vmin3_2(EA, EB, EC), hmin3_2(EB, lane));   /* E2[y-2] */     \
        HC = hmax3_2(maskneg2(FC, colok &&                                     \
                 (RIN || (unsigned)(y - 2) < (unsigned)HH)), lane);            \
        float2 e3_ = min2(vmin3_2(FA, FB, FC), hmin3_2(FB, lane)); /* y-3 */   \
        BC = hmax3_2(maskneg2(e3_, colok &&                                    \
                 (RIN || (unsigned)(y - 3) < (unsigned)HH)), lane);            \
        if (y >= yOUT) {                                     /* row y-4 */     \
            float2 D2 = vmax3_2(BA, BB, BC);                                   \
            if (stok) {                                                        \
                float2 d2 = relu_sub2(FA, D2);               /* E2[y-4] */     \
                float2 s = spf;                                                \
                skel_upd2(s, dprev);                                           \
                skel_upd2(s, d2);                                              \
                *(float2*)(skb + (y - 4) * WW) = s;                            \
                *(float2*)(dsb + (y - 4) * WW) = FA;                           \
            }                                                                  \
        }                                                                      \
        if (y >= yD1) {                                      /* delta1 y-3 */  \
            float2 D1 = vmax3_2(HA, HB, HC);                                   \
            dprev = relu_sub2(EA, D1);                       /* E1[y-3] */     \
            if (stok && (RIN || (unsigned)(y - 3) < (unsigned)HH))             \
                spf = *(const float2*)(skb + (y - 3) * WW);                    \
        }                                                                      \
        ++y;                                                                   \
    }

    // 24 steps = 8 groups of 3 (ring rotation by argument permutation)
#pragma unroll 1
    for (int k = 0; k < 8; ++k) {
        STEP2(ia, ib, ic, ea, eb, ec, fa, fb, fc, ha, hb, hc, ba, bb, bc);
        STEP2(ib, ic, ia, eb, ec, ea, fb, fc, fa, hb, hc, ha, bb, bc, ba);
        STEP2(ic, ia, ib, ec, ea, eb, fc, fa, fb, hc, ha, hb, bc, ba, bb);
    }
#undef STEP2
}

__global__ void __launch_bounds__(IT2_BLOCK, 8) k_iter2(int flip) {
    const int lane = threadIdx.x & 31;
    const int gw = (blockIdx.x * IT2_BLOCK + threadIdx.x) >> 5;
    const int strip = gw % STRIPS2;
    const int t = gw / STRIPS2;
    const int chunk = t & (CHUNKS - 1);
    const int z = t >> 5;

    const float* __restrict__ src = (flip ? g_imgB : g_imgA) + z * HWSZ;
    float* __restrict__ dst = (flip ? g_imgA : g_imgB) + z * HWSZ;
    float* __restrict__ skel = g_skel + z * HWSZ;
    const int r0 = chunk * CHUNK_ROWS;

    const bool rin = (chunk >= 1) && (chunk <= 30);
    const bool cin = (strip >= 1) && (strip <= 8);
    if (rin) {
        if (cin) it2_body<true, true>(src, dst, skel, lane, strip, r0);
        else     it2_body<true, false>(src, dst, skel, lane, strip, r0);
    } else {
        if (cin) it2_body<false, true>(src, dst, skel, lane, strip, r0);
        else     it2_body<false, false>(src, dst, skel, lane, strip, r0);
    }
}

// ---------------------------------------------------------------------------
// Reductions
// ---------------------------------------------------------------------------
__global__ void k_zero() {
    int t = threadIdx.x;
    if (t < NIMG * 7) ((double*)g_sums)[t] = 0.0;
}

__global__ void k_reduce(const float* __restrict__ tgt) {
    const int n = blockIdx.y;
    const float4* __restrict__ sp = (const float4*)(g_skel + n * HWSZ);
    const float4* __restrict__ sl = (const float4*)(g_skel + (NIMG + n) * HWSZ);
    const float4* __restrict__ pp = (const float4*)(g_p + n * HWSZ);
    const float4* __restrict__ tt = (const float4*)(tgt + n * HWSZ);
    const int n4 = HWSZ / 4;

    double a0 = 0, a1 = 0, a2 = 0, a3 = 0, a4 = 0, a5 = 0, a6 = 0;
    for (int i = blockIdx.x * blockDim.x + threadIdx.x; i < n4;
         i += gridDim.x * blockDim.x) {
        float4 s1 = sp[i], s2 = sl[i], pv = pp[i], tv = tt[i];
        a0 += (double)(s1.x * tv.x + s1.y * tv.y + s1.z * tv.z + s1.w * tv.w);
        a1 += (double)(s1.x + s1.y + s1.z + s1.w);
        a2 += (double)(s2.x * pv.x + s2.y * pv.y + s2.z * pv.z + s2.w * pv.w);
        a3 += (double)(s2.x + s2.y + s2.z + s2.w);
        a4 += (double)(pv.x * tv.x + pv.y * tv.y + pv.z * tv.z + pv.w * tv.w);
        a5 += (double)(pv.x + pv.y + pv.z + pv.w);
        a6 += (double)(tv.x + tv.y + tv.z + tv.w);
    }
#pragma unroll
    for (int o = 16; o > 0; o >>= 1) {
        a0 += __shfl_down_sync(0xffffffffu, a0, o);
        a1 += __shfl_down_sync(0xffffffffu, a1, o);
        a2 += __shfl_down_sync(0xffffffffu, a2, o);
        a3 += __shfl_down_sync(0xffffffffu, a3, o);
        a4 += __shfl_down_sync(0xffffffffu, a4, o);
        a5 += __shfl_down_sync(0xffffffffu, a5, o);
        a6 += __shfl_down_sync(0xffffffffu, a6, o);
    }
    if ((threadIdx.x & 31) == 0) {
        atomicAdd(&g_sums[n][0], a0);
        atomicAdd(&g_sums[n][1], a1);
        atomicAdd(&g_sums[n][2], a2);
        atomicAdd(&g_sums[n][3], a3);
        atomicAdd(&g_sums[n][4], a4);
        atomicAdd(&g_sums[n][5], a5);
        atomicAdd(&g_sums[n][6], a6);
    }
}

__global__ void k_final(float* __restrict__ out, int out_size) {
    if (threadIdx.x == 0 && blockIdx.x == 0) {
        const double smooth = 1.0;
        double cl = 0.0, dice = 0.0;
        for (int n = 0; n < NIMG; n++) {
            double A = g_sums[n][0], B = g_sums[n][1], C = g_sums[n][2],
                   D = g_sums[n][3], E = g_sums[n][4], F = g_sums[n][5],
                   G = g_sums[n][6];
            double tprec = (A + smooth) / (B + smooth);
            double tsens = (C + smooth) / (D + smooth);
            cl += 1.0 - 2.0 * tprec * tsens / (tprec + tsens);
            dice += 1.0 - 2.0 * (E + smooth) / (F + G + smooth);
        }
        cl /= NIMG;
        dice /= NIMG;
        float loss = (float)(0.7 * dice + 0.3 * cl);
        for (int i = 0; i < out_size; i++) out[i] = loss;
    }
}

// ---------------------------------------------------------------------------
extern "C" void kernel_launch(void* const* d_in, const int* in_sizes, int n_in,
                              void* d_out, int out_size) {
    const float* output = (const float*)d_in[0];
    const float* target = (const float*)d_in[1];
    float* out = (float*)d_out;

    k_init<<<1024, 256>>>((const float4*)output, (const float4*)target);

    k_open_init<<<SWEEP_GRID, SWEEP_BLOCK>>>();

    // 50 iterations = 25 fused-2 launches
    for (int j = 0; j < NITER / 2; ++j) {
        k_iter2<<<IT2_GRID, IT2_BLOCK>>>(j & 1);
    }

    k_zero<<<1, 64>>>();
    k_reduce<<<dim3(32, NIMG), 256>>>(target);
    k_final<<<1, 32>>>(out, out_size);
}